// round 10
// baseline (speedup 1.0000x reference)
#include <cuda_runtime.h>
#include <cstdint>

#define BB   128
#define TT   2048
#define DD   64
#define HH   256
#define OO   32
#define NBLK 128
#define NTHR 256
#define ACTSTR 12
#define CLSZ 16

// ---- static device scratch (no allocations) ----
__device__ float    g_P[(size_t)TT * BB * 1024];          // [t][blk=bg*16+cg][...]  (1 GiB)
__device__ float    g_hist[(size_t)(TT + 1) * BB * HH];   // [t][b][k]  (post-pass only)
__device__ unsigned g_cnt;
__device__ unsigned g_gen;

__global__ void reset_kernel() { g_cnt = 0u; g_gen = 0u; }

__device__ __forceinline__ float sigf(float x) {
    return 1.0f / (1.0f + __expf(-x));
}
__device__ __forceinline__ float tanh_fast(float x) {
    return 1.0f - 2.0f / (__expf(2.0f * x) + 1.0f);
}

__device__ __forceinline__ void fma2(uint64_t& acc, uint64_t a, uint64_t b) {
    asm("fma.rn.f32x2 %0, %1, %2, %0;" : "+l"(acc) : "l"(a), "l"(b));
}
__device__ __forceinline__ void add2(uint64_t& a, uint64_t b) {
    asm("add.rn.f32x2 %0, %0, %1;" : "+l"(a) : "l"(b));
}
__device__ __forceinline__ uint64_t pack2(float lo, float hi) {
    uint64_t r; asm("mov.b64 %0, {%1, %2};" : "=l"(r) : "f"(lo), "f"(hi)); return r;
}
__device__ __forceinline__ float2 unpack2(uint64_t v) {
    float2 r; asm("mov.b64 {%0, %1}, %2;" : "=f"(r.x), "=f"(r.y) : "l"(v)); return r;
}

#define FMA4(ACC, S, W) do { \
    (ACC).x = fmaf((S), (W).x, (ACC).x); \
    (ACC).y = fmaf((S), (W).y, (ACC).y); \
    (ACC).z = fmaf((S), (W).z, (ACC).z); \
    (ACC).w = fmaf((S), (W).w, (ACC).w); } while (0)

#define CLUSTER_SYNC() do { \
    asm volatile("barrier.cluster.arrive.aligned;" ::: "memory"); \
    asm volatile("barrier.cluster.wait.aligned;"   ::: "memory"); } while (0)

__device__ __forceinline__ void grid_bar(unsigned target) {
    __syncthreads();
    if (threadIdx.x == 0) {
        unsigned old;
        asm volatile("atom.acq_rel.gpu.add.u32 %0, [%1], %2;"
                     : "=r"(old) : "l"(&g_cnt), "r"(1u) : "memory");
        if (old == NBLK - 1u) {
            g_cnt = 0u;
            asm volatile("st.release.gpu.u32 [%0], %1;"
                         :: "l"(&g_gen), "r"(target) : "memory");
        } else {
            unsigned g;
            do {
                asm volatile("ld.acquire.gpu.u32 %0, [%1];"
                             : "=r"(g) : "l"(&g_gen) : "memory");
            } while (g < target);
        }
    }
    __syncthreads();
}

// interleaved global col gi = pair_glob*8 + o, o = gate*2 + jj (f0 f1 i0 i1 z0 z1 r0 r1)
__device__ __forceinline__ float w_elem(int gi, int d,
                                        const float* __restrict__ kfiz,
                                        const float* __restrict__ kr)
{
    int pairg = gi >> 3, o = gi & 7;
    int gate = o >> 1, jj = o & 1;
    int unit = pairg * 2 + jj;
    return (gate < 3) ? kfiz[(size_t)d * 768 + gate * HH + unit]
                      : kr[(size_t)d * HH + unit];
}
__device__ __forceinline__ float b_elem(int gi,
                                        const float* __restrict__ bfiz,
                                        const float* __restrict__ br)
{
    int pairg = gi >> 3, o = gi & 7;
    int gate = o >> 1, jj = o & 1;
    int unit = pairg * 2 + jj;
    return (gate < 3) ? bfiz[gate * HH + unit] : br[unit];
}

// =============== pre-pass: P = u_t @ W_u + bias ===============
// P[t][blk = bg*16 + cg][ (b&15)*64 + pl*8 + o ]
__global__ void __launch_bounds__(256, 1)
pre_kernel(const float* __restrict__ u, const float* __restrict__ kfiz,
           const float* __restrict__ bfiz, const float* __restrict__ kr,
           const float* __restrict__ br)
{
    extern __shared__ float sm[];
    float* u_sh = sm;             // 8192 floats
    float* W_sh = sm + 128 * 64;  // 32768 floats  [d][512 interleaved cols]

    const int t = blockIdx.x, ch = blockIdx.y, tid = threadIdx.x;

    #pragma unroll
    for (int j = 0; j < 8; ++j) {
        int idx4 = tid + j * 256;
        int b = idx4 >> 4, d4 = (idx4 & 15) << 2;
        *(float4*)&u_sh[b * 64 + d4] =
            *(const float4*)&u[((size_t)b * TT + t) * DD + d4];
    }
    #pragma unroll
    for (int j = 0; j < 128; ++j) {
        int idx = tid + j * 256;
        int d = idx >> 9, cl = idx & 511;
        W_sh[idx] = w_elem(ch * 512 + cl, d, kfiz, kr);
    }
    const int cgid = tid & 127, bh = tid >> 7;
    const int c0 = ch * 512 + cgid * 4;
    float4 bias4;
    bias4.x = b_elem(c0 + 0, bfiz, br);
    bias4.y = b_elem(c0 + 1, bfiz, br);
    bias4.z = b_elem(c0 + 2, bfiz, br);
    bias4.w = b_elem(c0 + 3, bfiz, br);
    __syncthreads();

    const int pair_glob = c0 >> 3, o0 = c0 & 7;    // o0 in {0,4}
    const int cgp = pair_glob >> 3, pl = pair_glob & 7;
    // blk = bg*16 + cgp, bg = b>>4
    float* pbase = g_P + ((size_t)t * 128 + cgp) * 1024 + pl * 8 + o0;

    for (int bt = 0; bt < 4; ++bt) {
        float4 acc[16];
        #pragma unroll
        for (int ib = 0; ib < 16; ++ib) acc[ib] = bias4;
        #pragma unroll
        for (int dt = 0; dt < 8; ++dt) {
            float4 w[8];
            #pragma unroll
            for (int e = 0; e < 8; ++e)
                w[e] = *(float4*)&W_sh[(dt * 8 + e) * 512 + cgid * 4];
            #pragma unroll
            for (int ib = 0; ib < 16; ++ib) {
                int b = bh * 64 + bt * 16 + ib;
                float4 aA = *(float4*)&u_sh[b * 64 + dt * 8];
                float4 aB = *(float4*)&u_sh[b * 64 + dt * 8 + 4];
                FMA4(acc[ib], aA.x, w[0]); FMA4(acc[ib], aA.y, w[1]);
                FMA4(acc[ib], aA.z, w[2]); FMA4(acc[ib], aA.w, w[3]);
                FMA4(acc[ib], aB.x, w[4]); FMA4(acc[ib], aB.y, w[5]);
                FMA4(acc[ib], aB.z, w[6]); FMA4(acc[ib], aB.w, w[7]);
            }
        }
        #pragma unroll
        for (int ib = 0; ib < 16; ++ib) {
            int b = bh * 64 + bt * 16 + ib;
            *(float4*)(pbase + (size_t)(b >> 4) * (16 * 1024) + (b & 15) * 64) = acc[ib];
        }
    }
}

// ---- shared serial-kernel helpers (weight load identical in both variants) ----
__device__ __forceinline__ void load_wp(uint64_t wp[16][2], int cg, int ksl, int cq,
                                        const float* __restrict__ kfiz,
                                        const float* __restrict__ kr)
{
    const int pair_glob = cg * 8 + (cq >> 1);
    const int oh = cq & 1;
    #pragma unroll
    for (int j = 0; j < 16; ++j) {
        float wv[4];
        #pragma unroll
        for (int c = 0; c < 4; ++c) {
            int o = oh * 4 + c, gate = o >> 1, jj = o & 1;
            int unit = pair_glob * 2 + jj;
            int row = DD + ksl * 16 + j;
            wv[c] = (gate < 3) ? kfiz[(size_t)row * 768 + gate * HH + unit]
                               : kr[(size_t)row * HH + unit];
        }
        wp[j][0] = pack2(wv[0], wv[1]);
        wp[j][1] = pack2(wv[2], wv[3]);
    }
}

#define STEPK(HV, K) do { uint64_t hd_ = pack2((HV), (HV)); \
    fma2(a0_, hd_, wp[K][0]); fma2(a1_, hd_, wp[K][1]); } while (0)

// =============== serial recurrence, 16-CTA cluster + DSMEM h-exchange ===============
// 128 blocks = 8 bg-clusters x 16 cg. Block bid: cg = bid&15, bg = bid>>4.
// Cols: units [cg*16, cg*16+16); batches [bg*16, bg*16+16).
__global__ void __launch_bounds__(256, 1)
serial_cluster(const float* __restrict__ x0, const float* __restrict__ kfiz,
               const float* __restrict__ kr)
{
    extern __shared__ float sm[];
    float* part = sm;                     // [16 ksl][16 b][64 l] = 16384 floats
    float* act  = sm + 16384;             // [16 b][8 pair][12]   = 1536 floats
    float* hsh  = sm + 16384 + 1536;      // [2][16 b][256]       = 8192 floats

    const int tid = threadIdx.x, bid = blockIdx.x;
    const int cg = bid & 15, bg = bid >> 4;
    const int ksl = tid >> 4, cq = tid & 15;   // also (bu, jl) roles

    uint64_t wp[16][2];
    load_wp(wp, cg, ksl, cq, kfiz, kr);

    const int bu = ksl, jl = cq;
    float c = x0[(size_t)(bg * 16 + bu) * (2 * HH) + HH + cg * 16 + jl];

    // init h_sh buffer 0 with h0 for this bg (each block loads its own copy)
    #pragma unroll
    for (int q = 0; q < 4; ++q) {
        int idx4 = tid + q * 256;
        int bl = idx4 >> 6, k4 = (idx4 & 63) * 4;
        *(float4*)&hsh[bl * 256 + k4] =
            *(const float4*)&x0[(size_t)(bg * 16 + bl) * (2 * HH) + k4];
    }
    uint32_t hbase_u32;
    asm("{ .reg .u64 t0; cvta.to.shared.u64 t0, %1; cvt.u32.u64 %0, t0; }"
        : "=r"(hbase_u32) : "l"(hsh));
    __syncthreads();
    CLUSTER_SYNC();

    for (int t = 0; t < TT; ++t) {
        ulonglong2 pvv =
            __ldcg((const ulonglong2*)(g_P + ((size_t)t * 128 + bid) * 1024) + tid);
        const float* hc = hsh + (t & 1) * 4096 + ksl * 16;

        #pragma unroll
        for (int b = 0; b < 16; ++b) {
            const float4* hp = (const float4*)(hc + b * 256);
            float4 h0 = hp[0], h1 = hp[1], h2 = hp[2], h3 = hp[3];
            uint64_t a0_ = 0ull, a1_ = 0ull;
            STEPK(h0.x,  0); STEPK(h0.y,  1); STEPK(h0.z,  2); STEPK(h0.w,  3);
            STEPK(h1.x,  4); STEPK(h1.y,  5); STEPK(h1.z,  6); STEPK(h1.w,  7);
            STEPK(h2.x,  8); STEPK(h2.y,  9); STEPK(h2.z, 10); STEPK(h2.w, 11);
            STEPK(h3.x, 12); STEPK(h3.y, 13); STEPK(h3.z, 14); STEPK(h3.w, 15);
            float2 p0 = unpack2(a0_);
            float2 p1 = unpack2(a1_);
            *(float4*)&part[ksl * 1024 + b * 64 + cq * 4] =
                make_float4(p0.x, p0.y, p1.x, p1.y);
        }
        __syncthreads();

        {   // reduce + activate
            uint64_t s0 = pvv.x, s1 = pvv.y;
            #pragma unroll
            for (int k2 = 0; k2 < 16; ++k2) {
                ulonglong2 q = *(const ulonglong2*)&part[k2 * 1024 + tid * 4];
                add2(s0, q.x); add2(s1, q.y);
            }
            float2 f01 = unpack2(s0), f23 = unpack2(s1);
            float v0 = f01.x, v1 = f01.y, v2 = f23.x, v3 = f23.y;
            const int ohr = tid & 1;
            if (ohr == 0) { v0 = sigf(v0); v1 = sigf(v1); v2 = sigf(v2); v3 = sigf(v3); }
            else          { v0 = sigf(v0); v1 = sigf(v1);
                            v2 = tanh_fast(v2); v3 = tanh_fast(v3); }
            const int br = tid >> 4, plr = (tid >> 1) & 7;
            *(float4*)&act[(br * 8 + plr) * ACTSTR + ohr * 4] =
                make_float4(v0, v1, v2, v3);
        }
        __syncthreads();

        {   // c/h update + DSMEM broadcast of h_new to all 16 cluster CTAs
            const int pair = jl >> 1, jj = jl & 1;
            const float* g = act + (bu * 8 + pair) * ACTSTR;
            float f = g[jj], ii = g[2 + jj], z = g[4 + jj], r = g[6 + jj];
            c = fmaf(f, c, ii * r);
            float hv = z * tanh_fast(c);
            g_hist[(size_t)(t + 1) * (BB * HH)
                   + (size_t)(bg * 16 + bu) * HH + cg * 16 + jl] = hv;
            uint32_t loff = hbase_u32 +
                (uint32_t)((((t + 1) & 1) * 4096 + bu * 256 + cg * 16 + jl) * 4);
            #pragma unroll
            for (int rnk = 0; rnk < CLSZ; ++rnk) {
                uint32_t ra;
                asm("mapa.shared::cluster.u32 %0, %1, %2;"
                    : "=r"(ra) : "r"(loff), "r"(rnk));
                asm volatile("st.shared::cluster.f32 [%0], %1;"
                             :: "r"(ra), "f"(hv) : "memory");
            }
        }
        CLUSTER_SYNC();   // release remote h stores; acquire peers'
    }
}

// =============== fallback serial (grid barrier, same P/bid layout) ===============
__global__ void __launch_bounds__(256, 1)
serial_fb(const float* __restrict__ x0, const float* __restrict__ kfiz,
          const float* __restrict__ kr)
{
    extern __shared__ float sm[];
    float* part = sm;
    float* act  = sm + 16384;

    const int tid = threadIdx.x, bid = blockIdx.x;
    const int cg = bid & 15, bg = bid >> 4;
    const int ksl = tid >> 4, cq = tid & 15;

    uint64_t wp[16][2];
    load_wp(wp, cg, ksl, cq, kfiz, kr);

    const int bu = ksl, jl = cq;
    float c = x0[(size_t)(bg * 16 + bu) * (2 * HH) + HH + cg * 16 + jl];

    if (cg == 0) {
        #pragma unroll
        for (int q = 0; q < 4; ++q) {
            int idx4 = tid + q * 256;
            int bl = idx4 >> 6, k4 = (idx4 & 63) * 4;
            *(float4*)&g_hist[(size_t)(bg * 16 + bl) * HH + k4] =
                *(const float4*)&x0[(size_t)(bg * 16 + bl) * (2 * HH) + k4];
        }
    }
    grid_bar(1u);

    for (int t = 0; t < TT; ++t) {
        ulonglong2 pvv =
            __ldcg((const ulonglong2*)(g_P + ((size_t)t * 128 + bid) * 1024) + tid);
        const float* hb = g_hist + (size_t)t * (BB * HH)
                        + (size_t)(bg * 16) * HH + ksl * 16;

        #pragma unroll
        for (int b = 0; b < 16; ++b) {
            const float4* hp = (const float4*)(hb + (size_t)b * HH);
            float4 h0 = __ldcg(hp + 0);
            float4 h1 = __ldcg(hp + 1);
            float4 h2 = __ldcg(hp + 2);
            float4 h3 = __ldcg(hp + 3);
            uint64_t a0_ = 0ull, a1_ = 0ull;
            STEPK(h0.x,  0); STEPK(h0.y,  1); STEPK(h0.z,  2); STEPK(h0.w,  3);
            STEPK(h1.x,  4); STEPK(h1.y,  5); STEPK(h1.z,  6); STEPK(h1.w,  7);
            STEPK(h2.x,  8); STEPK(h2.y,  9); STEPK(h2.z, 10); STEPK(h2.w, 11);
            STEPK(h3.x, 12); STEPK(h3.y, 13); STEPK(h3.z, 14); STEPK(h3.w, 15);
            float2 p0 = unpack2(a0_);
            float2 p1 = unpack2(a1_);
            *(float4*)&part[ksl * 1024 + b * 64 + cq * 4] =
                make_float4(p0.x, p0.y, p1.x, p1.y);
        }
        __syncthreads();

        {
            uint64_t s0 = pvv.x, s1 = pvv.y;
            #pragma unroll
            for (int k2 = 0; k2 < 16; ++k2) {
                ulonglong2 q = *(const ulonglong2*)&part[k2 * 1024 + tid * 4];
                add2(s0, q.x); add2(s1, q.y);
            }
            float2 f01 = unpack2(s0), f23 = unpack2(s1);
            float v0 = f01.x, v1 = f01.y, v2 = f23.x, v3 = f23.y;
            const int ohr = tid & 1;
            if (ohr == 0) { v0 = sigf(v0); v1 = sigf(v1); v2 = sigf(v2); v3 = sigf(v3); }
            else          { v0 = sigf(v0); v1 = sigf(v1);
                            v2 = tanh_fast(v2); v3 = tanh_fast(v3); }
            const int br = tid >> 4, plr = (tid >> 1) & 7;
            *(float4*)&act[(br * 8 + plr) * ACTSTR + ohr * 4] =
                make_float4(v0, v1, v2, v3);
        }
        __syncthreads();

        {
            const int pair = jl >> 1, jj = jl & 1;
            const float* g = act + (bu * 8 + pair) * ACTSTR;
            float f = g[jj], ii = g[2 + jj], z = g[4 + jj], r = g[6 + jj];
            c = fmaf(f, c, ii * r);
            g_hist[(size_t)(t + 1) * (BB * HH)
                   + (size_t)(bg * 16 + bu) * HH + cg * 16 + jl] = z * tanh_fast(c);
        }
        grid_bar((unsigned)(t + 2));
    }
}

// =============== post-pass: y[b][t][:] = h_t @ W_out + b_out ===============
__global__ void __launch_bounds__(256, 1)
post_kernel(const float* __restrict__ Wout, const float* __restrict__ bout,
            float* __restrict__ out)
{
    extern __shared__ float sm[];
    float* H_sh  = sm;              // [128][264]
    float* W_sh  = sm + 128 * 264;  // [256][32]
    float* bo_sh = W_sh + 256 * 32; // [32]

    const int t = blockIdx.x, tid = threadIdx.x;
    const float* hrow = g_hist + (size_t)(t + 1) * (BB * HH);

    #pragma unroll
    for (int j = 0; j < 32; ++j) {
        int idx4 = tid + j * 256;
        int b = idx4 >> 6, k4 = (idx4 & 63) << 2;
        *(float4*)&H_sh[b * 264 + k4] = __ldcg((const float4*)(hrow + b * HH + k4));
    }
    #pragma unroll
    for (int j = 0; j < 32; ++j) {
        int idx = tid + j * 256;
        W_sh[idx] = Wout[idx];
    }
    if (tid < 32) bo_sh[tid] = bout[tid];
    __syncthreads();

    const int b = tid >> 1, oh = tid & 1;
    float4 acc[4];
    #pragma unroll
    for (int q = 0; q < 4; ++q)
        acc[q] = *(float4*)&bo_sh[oh * 16 + q * 4];

    const float* hb = H_sh + b * 264;
    #pragma unroll 4
    for (int k = 0; k < 256; ++k) {
        float a = hb[k];
        const float* wr = W_sh + k * 32 + oh * 16;
        #pragma unroll
        for (int q = 0; q < 4; ++q) {
            float4 wv = *(const float4*)(wr + q * 4);
            FMA4(acc[q], a, wv);
        }
    }
    float* ob = out + ((size_t)b * TT + t) * OO + oh * 16;
    #pragma unroll
    for (int q = 0; q < 4; ++q) *(float4*)(ob + q * 4) = acc[q];
}

extern "C" void kernel_launch(void* const* d_in, const int* in_sizes, int n_in,
                              void* d_out, int out_size)
{
    const float* u    = (const float*)d_in[0];
    const float* x0   = (const float*)d_in[1];
    const float* kfiz = (const float*)d_in[2];
    const float* bfiz = (const float*)d_in[3];
    const float* kr   = (const float*)d_in[4];
    const float* br   = (const float*)d_in[5];
    const float* Wout = (const float*)d_in[6];
    const float* bout = (const float*)d_in[7];
    float* out = (float*)d_out;

    const size_t preSmem  = (size_t)(128 * 64 + 64 * 512) * sizeof(float);       // 163,840
    const size_t clSmem   = (size_t)(16384 + 1536 + 8192) * sizeof(float);       // 104,448
    const size_t fbSmem   = 131072;
    const size_t postSmem = (size_t)(128 * 264 + 256 * 32 + 32) * sizeof(float); // 168,064

    cudaFuncSetAttribute(pre_kernel,  cudaFuncAttributeMaxDynamicSharedMemorySize, (int)preSmem);
    cudaFuncSetAttribute(post_kernel, cudaFuncAttributeMaxDynamicSharedMemorySize, (int)postSmem);
    cudaFuncSetAttribute(serial_fb,   cudaFuncAttributeMaxDynamicSharedMemorySize, (int)fbSmem);

    pre_kernel<<<dim3(TT, 2), NTHR, preSmem>>>(u, kfiz, bfiz, kr, br);

    bool cluster_ok = true;
    if (cudaFuncSetAttribute(serial_cluster,
            cudaFuncAttributeNonPortableClusterSizeAllowed, 1) != cudaSuccess)
        cluster_ok = false;
    if (cluster_ok && cudaFuncSetAttribute(serial_cluster,
            cudaFuncAttributeMaxDynamicSharedMemorySize, (int)clSmem) != cudaSuccess)
        cluster_ok = false;

    if (cluster_ok) {
        cudaLaunchConfig_t cfg = {};
        cfg.gridDim  = dim3(NBLK, 1, 1);
        cfg.blockDim = dim3(NTHR, 1, 1);
        cfg.dynamicSmemBytes = clSmem;
        cfg.stream = 0;
        cudaLaunchAttribute at[1];
        at[0].id = cudaLaunchAttributeClusterDimension;
        at[0].val.clusterDim.x = CLSZ;
        at[0].val.clusterDim.y = 1;
        at[0].val.clusterDim.z = 1;
        cfg.attrs = at;
        cfg.numAttrs = 1;
        if (cudaLaunchKernelEx(&cfg, serial_cluster, x0, kfiz, kr) != cudaSuccess)
            cluster_ok = false;
    }
    if (!cluster_ok) {
        cudaGetLastError();  // clear sticky launch error state
        reset_kernel<<<1, 1>>>();
        serial_fb<<<NBLK, NTHR, fbSmem>>>(x0, kfiz, kr);
    }

    post_kernel<<<TT, NTHR, postSmem>>>(Wout, bout, out);
}

// round 11
// speedup vs baseline: 1.8792x; 1.8792x over previous
#include <cuda_runtime.h>
#include <cstdint>

#define BB   128
#define TT   2048
#define DD   64
#define HH   256
#define OO   32
#define NBLK 128
#define NTHR 256
#define ACTSTR 12

// ---- static device scratch (no allocations) ----
__device__ float    g_P[(size_t)TT * BB * 1024];          // [t][blk=bg*16+cg][...]  (1 GiB)
__device__ float    g_hist[(size_t)(TT + 1) * BB * HH];   // [t][b][k]
__device__ unsigned g_flag[NBLK * 32];                    // one flag per block, 128B apart

__global__ void reset_kernel() {
    for (int i = threadIdx.x; i < NBLK * 32; i += 256) g_flag[i] = 0u;
}

__device__ __forceinline__ float sigf(float x) {
    return 1.0f / (1.0f + __expf(-x));
}
__device__ __forceinline__ float tanh_fast(float x) {
    return 1.0f - 2.0f / (__expf(2.0f * x) + 1.0f);
}

__device__ __forceinline__ void fma2(uint64_t& acc, uint64_t a, uint64_t b) {
    asm("fma.rn.f32x2 %0, %1, %2, %0;" : "+l"(acc) : "l"(a), "l"(b));
}
__device__ __forceinline__ void add2(uint64_t& a, uint64_t b) {
    asm("add.rn.f32x2 %0, %0, %1;" : "+l"(a) : "l"(b));
}
__device__ __forceinline__ uint64_t pack2(float lo, float hi) {
    uint64_t r; asm("mov.b64 %0, {%1, %2};" : "=l"(r) : "f"(lo), "f"(hi)); return r;
}
__device__ __forceinline__ float2 unpack2(uint64_t v) {
    float2 r; asm("mov.b64 {%0, %1}, %2;" : "=f"(r.x), "=f"(r.y) : "l"(v)); return r;
}

#define FMA4(ACC, S, W) do { \
    (ACC).x = fmaf((S), (W).x, (ACC).x); \
    (ACC).y = fmaf((S), (W).y, (ACC).y); \
    (ACC).z = fmaf((S), (W).z, (ACC).z); \
    (ACC).w = fmaf((S), (W).w, (ACC).w); } while (0)

// interleaved global col gi = pair_glob*8 + o, o = gate*2 + jj (f0 f1 i0 i1 z0 z1 r0 r1)
__device__ __forceinline__ float w_elem(int gi, int d,
                                        const float* __restrict__ kfiz,
                                        const float* __restrict__ kr)
{
    int pairg = gi >> 3, o = gi & 7;
    int gate = o >> 1, jj = o & 1;
    int unit = pairg * 2 + jj;
    return (gate < 3) ? kfiz[(size_t)d * 768 + gate * HH + unit]
                      : kr[(size_t)d * HH + unit];
}
__device__ __forceinline__ float b_elem(int gi,
                                        const float* __restrict__ bfiz,
                                        const float* __restrict__ br)
{
    int pairg = gi >> 3, o = gi & 7;
    int gate = o >> 1, jj = o & 1;
    int unit = pairg * 2 + jj;
    return (gate < 3) ? bfiz[gate * HH + unit] : br[unit];
}

// =============== pre-pass: P = u_t @ W_u + bias ===============
// P[t][blk = bg*16 + cg][ (b&15)*64 + pl*8 + o ]
__global__ void __launch_bounds__(256, 1)
pre_kernel(const float* __restrict__ u, const float* __restrict__ kfiz,
           const float* __restrict__ bfiz, const float* __restrict__ kr,
           const float* __restrict__ br)
{
    extern __shared__ float sm[];
    float* u_sh = sm;             // 8192 floats
    float* W_sh = sm + 128 * 64;  // 32768 floats  [d][512 interleaved cols]

    const int t = blockIdx.x, ch = blockIdx.y, tid = threadIdx.x;

    #pragma unroll
    for (int j = 0; j < 8; ++j) {
        int idx4 = tid + j * 256;
        int b = idx4 >> 4, d4 = (idx4 & 15) << 2;
        *(float4*)&u_sh[b * 64 + d4] =
            *(const float4*)&u[((size_t)b * TT + t) * DD + d4];
    }
    #pragma unroll
    for (int j = 0; j < 128; ++j) {
        int idx = tid + j * 256;
        int d = idx >> 9, cl = idx & 511;
        W_sh[idx] = w_elem(ch * 512 + cl, d, kfiz, kr);
    }
    const int cgid = tid & 127, bh = tid >> 7;
    const int c0 = ch * 512 + cgid * 4;
    float4 bias4;
    bias4.x = b_elem(c0 + 0, bfiz, br);
    bias4.y = b_elem(c0 + 1, bfiz, br);
    bias4.z = b_elem(c0 + 2, bfiz, br);
    bias4.w = b_elem(c0 + 3, bfiz, br);
    __syncthreads();

    const int pair_glob = c0 >> 3, o0 = c0 & 7;    // o0 in {0,4}
    const int cgp = pair_glob >> 3, pl = pair_glob & 7;
    // blk = bg*16 + cgp, bg = b>>4
    float* pbase = g_P + ((size_t)t * 128 + cgp) * 1024 + pl * 8 + o0;

    for (int bt = 0; bt < 4; ++bt) {
        float4 acc[16];
        #pragma unroll
        for (int ib = 0; ib < 16; ++ib) acc[ib] = bias4;
        #pragma unroll
        for (int dt = 0; dt < 8; ++dt) {
            float4 w[8];
            #pragma unroll
            for (int e = 0; e < 8; ++e)
                w[e] = *(float4*)&W_sh[(dt * 8 + e) * 512 + cgid * 4];
            #pragma unroll
            for (int ib = 0; ib < 16; ++ib) {
                int b = bh * 64 + bt * 16 + ib;
                float4 aA = *(float4*)&u_sh[b * 64 + dt * 8];
                float4 aB = *(float4*)&u_sh[b * 64 + dt * 8 + 4];
                FMA4(acc[ib], aA.x, w[0]); FMA4(acc[ib], aA.y, w[1]);
                FMA4(acc[ib], aA.z, w[2]); FMA4(acc[ib], aA.w, w[3]);
                FMA4(acc[ib], aB.x, w[4]); FMA4(acc[ib], aB.y, w[5]);
                FMA4(acc[ib], aB.z, w[6]); FMA4(acc[ib], aB.w, w[7]);
            }
        }
        #pragma unroll
        for (int ib = 0; ib < 16; ++ib) {
            int b = bh * 64 + bt * 16 + ib;
            *(float4*)(pbase + (size_t)(b >> 4) * (16 * 1024) + (b & 15) * 64) = acc[ib];
        }
    }
}

// =============== serial recurrence, dataflow flags ===============
// 128 blocks: cg = bid&15, bg = bid>>4.
// Block (cg,bg): units [cg*16, cg*16+16), batches [bg*16, bg*16+16).
// h[t] ready for group bg when flag[bg*16+i] >= t+1 for all i.
__global__ void __launch_bounds__(256, 1)
serial_kernel(const float* __restrict__ x0, const float* __restrict__ kfiz,
              const float* __restrict__ kr)
{
    extern __shared__ float sm[];
    float* part = sm;             // [16 ksl][16 b][64 l] = 16384 floats
    float* act  = sm + 16384;     // [16 b][8 pair][12]   = 1536 floats

    const int tid = threadIdx.x, bid = blockIdx.x;
    const int cg = bid & 15, bg = bid >> 4;
    const int ksl = tid >> 4, cq = tid & 15;

    // packed weights: thread covers cols l = cq*4..+3, k rows ksl*16..+15
    uint64_t wp[16][2];
    {
        const int pair_glob = cg * 8 + (cq >> 1);
        const int oh = cq & 1;
        #pragma unroll
        for (int j = 0; j < 16; ++j) {
            float wv[4];
            #pragma unroll
            for (int c = 0; c < 4; ++c) {
                int o = oh * 4 + c, gate = o >> 1, jj = o & 1;
                int unit = pair_glob * 2 + jj;
                int row = DD + ksl * 16 + j;
                wv[c] = (gate < 3) ? kfiz[(size_t)row * 768 + gate * HH + unit]
                                   : kr[(size_t)row * HH + unit];
            }
            wp[j][0] = pack2(wv[0], wv[1]);
            wp[j][1] = pack2(wv[2], wv[3]);
        }
    }

    const int bu = ksl, jl = cq;   // c/h-update roles
    float c = x0[(size_t)(bg * 16 + bu) * (2 * HH) + HH + cg * 16 + jl];

    if (cg == 0) {   // publish h0 for this bg's 16 batches
        #pragma unroll
        for (int q = 0; q < 4; ++q) {
            int idx4 = tid + q * 256;
            int bl = idx4 >> 6, k4 = (idx4 & 63) * 4;
            *(float4*)&g_hist[(size_t)(bg * 16 + bl) * HH + k4] =
                *(const float4*)&x0[(size_t)(bg * 16 + bl) * (2 * HH) + k4];
        }
    }
    __syncthreads();
    if (tid == 0)    // every block raises its own flag to 1 (cg0's means "h0 ready")
        asm volatile("st.release.gpu.u32 [%0], %1;"
                     :: "l"(&g_flag[bid * 32]), "r"(1u) : "memory");

#define STEPK(HV, K) do { uint64_t hd_ = pack2((HV), (HV)); \
    fma2(a0_, hd_, wp[K][0]); fma2(a1_, hd_, wp[K][1]); } while (0)

    for (int t = 0; t < TT; ++t) {
        ulonglong2 pvv =
            __ldcg((const ulonglong2*)(g_P + ((size_t)t * 128 + bid) * 1024) + tid);

        // wait for all 16 producers of h[t] in this bg group
        if (tid < 16) {
            const unsigned* fp = &g_flag[(bg * 16 + tid) * 32];
            unsigned v;
            do {
                asm volatile("ld.acquire.gpu.u32 %0, [%1];"
                             : "=r"(v) : "l"(fp) : "memory");
            } while (v < (unsigned)(t + 1));
        }
        __syncthreads();

        const float* hb = g_hist + (size_t)t * (BB * HH)
                        + (size_t)(bg * 16) * HH + ksl * 16;

        #pragma unroll
        for (int b = 0; b < 16; ++b) {
            const float4* hp = (const float4*)(hb + (size_t)b * HH);
            float4 h0 = __ldcg(hp + 0);
            float4 h1 = __ldcg(hp + 1);
            float4 h2 = __ldcg(hp + 2);
            float4 h3 = __ldcg(hp + 3);
            uint64_t a0_ = 0ull, a1_ = 0ull;
            STEPK(h0.x,  0); STEPK(h0.y,  1); STEPK(h0.z,  2); STEPK(h0.w,  3);
            STEPK(h1.x,  4); STEPK(h1.y,  5); STEPK(h1.z,  6); STEPK(h1.w,  7);
            STEPK(h2.x,  8); STEPK(h2.y,  9); STEPK(h2.z, 10); STEPK(h2.w, 11);
            STEPK(h3.x, 12); STEPK(h3.y, 13); STEPK(h3.z, 14); STEPK(h3.w, 15);
            float2 p0 = unpack2(a0_);
            float2 p1 = unpack2(a1_);
            *(float4*)&part[ksl * 1024 + b * 64 + cq * 4] =
                make_float4(p0.x, p0.y, p1.x, p1.y);
        }
        __syncthreads();

        {   // reduce over 16 k-slices (+ P), activate
            uint64_t s0 = pvv.x, s1 = pvv.y;
            #pragma unroll
            for (int k2 = 0; k2 < 16; ++k2) {
                ulonglong2 q = *(const ulonglong2*)&part[k2 * 1024 + tid * 4];
                add2(s0, q.x); add2(s1, q.y);
            }
            float2 f01 = unpack2(s0), f23 = unpack2(s1);
            float v0 = f01.x, v1 = f01.y, v2 = f23.x, v3 = f23.y;
            const int ohr = tid & 1;
            if (ohr == 0) { v0 = sigf(v0); v1 = sigf(v1); v2 = sigf(v2); v3 = sigf(v3); }
            else          { v0 = sigf(v0); v1 = sigf(v1);
                            v2 = tanh_fast(v2); v3 = tanh_fast(v3); }
            const int br = tid >> 4, plr = (tid >> 1) & 7;
            *(float4*)&act[(br * 8 + plr) * ACTSTR + ohr * 4] =
                make_float4(v0, v1, v2, v3);
        }
        __syncthreads();

        {   // c/h update: thread (bu, jl) writes h[t+1]
            const int pair = jl >> 1, jj = jl & 1;
            const float* g = act + (bu * 8 + pair) * ACTSTR;
            float f = g[jj], ii = g[2 + jj], z = g[4 + jj], r = g[6 + jj];
            c = fmaf(f, c, ii * r);
            g_hist[(size_t)(t + 1) * (BB * HH)
                   + (size_t)(bg * 16 + bu) * HH + cg * 16 + jl] = z * tanh_fast(c);
        }
        __syncthreads();
        if (tid == 0)   // publish: h[t+1] from this block is ready
            asm volatile("st.release.gpu.u32 [%0], %1;"
                         :: "l"(&g_flag[bid * 32]), "r"((unsigned)(t + 2)) : "memory");
    }
#undef STEPK
}

// =============== post-pass: y[b][t][:] = h_t @ W_out + b_out ===============
__global__ void __launch_bounds__(256, 1)
post_kernel(const float* __restrict__ Wout, const float* __restrict__ bout,
            float* __restrict__ out)
{
    extern __shared__ float sm[];
    float* H_sh  = sm;              // [128][264]
    float* W_sh  = sm + 128 * 264;  // [256][32]
    float* bo_sh = W_sh + 256 * 32; // [32]

    const int t = blockIdx.x, tid = threadIdx.x;
    const float* hrow = g_hist + (size_t)(t + 1) * (BB * HH);

    #pragma unroll
    for (int j = 0; j < 32; ++j) {
        int idx4 = tid + j * 256;
        int b = idx4 >> 6, k4 = (idx4 & 63) << 2;
        *(float4*)&H_sh[b * 264 + k4] = __ldcg((const float4*)(hrow + b * HH + k4));
    }
    #pragma unroll
    for (int j = 0; j < 32; ++j) {
        int idx = tid + j * 256;
        W_sh[idx] = Wout[idx];
    }
    if (tid < 32) bo_sh[tid] = bout[tid];
    __syncthreads();

    const int b = tid >> 1, oh = tid & 1;
    float4 acc[4];
    #pragma unroll
    for (int q = 0; q < 4; ++q)
        acc[q] = *(float4*)&bo_sh[oh * 16 + q * 4];

    const float* hb = H_sh + b * 264;
    #pragma unroll 4
    for (int k = 0; k < 256; ++k) {
        float a = hb[k];
        const float* wr = W_sh + k * 32 + oh * 16;
        #pragma unroll
        for (int q = 0; q < 4; ++q) {
            float4 wv = *(const float4*)(wr + q * 4);
            FMA4(acc[q], a, wv);
        }
    }
    float* ob = out + ((size_t)b * TT + t) * OO + oh * 16;
    #pragma unroll
    for (int q = 0; q < 4; ++q) *(float4*)(ob + q * 4) = acc[q];
}

extern "C" void kernel_launch(void* const* d_in, const int* in_sizes, int n_in,
                              void* d_out, int out_size)
{
    const float* u    = (const float*)d_in[0];
    const float* x0   = (const float*)d_in[1];
    const float* kfiz = (const float*)d_in[2];
    const float* bfiz = (const float*)d_in[3];
    const float* kr   = (const float*)d_in[4];
    const float* br   = (const float*)d_in[5];
    const float* Wout = (const float*)d_in[6];
    const float* bout = (const float*)d_in[7];
    float* out = (float*)d_out;

    const size_t preSmem  = (size_t)(128 * 64 + 64 * 512) * sizeof(float);       // 163,840
    const size_t serSmem  = 131072;  // 71,680 used; padded to force 1 block/SM
    const size_t postSmem = (size_t)(128 * 264 + 256 * 32 + 32) * sizeof(float); // 168,064

    cudaFuncSetAttribute(pre_kernel,    cudaFuncAttributeMaxDynamicSharedMemorySize, (int)preSmem);
    cudaFuncSetAttribute(serial_kernel, cudaFuncAttributeMaxDynamicSharedMemorySize, (int)serSmem);
    cudaFuncSetAttribute(post_kernel,   cudaFuncAttributeMaxDynamicSharedMemorySize, (int)postSmem);

    reset_kernel<<<1, 256>>>();
    pre_kernel<<<dim3(TT, 2), NTHR, preSmem>>>(u, kfiz, bfiz, kr, br);
    serial_kernel<<<NBLK, NTHR, serSmem>>>(x0, kfiz, kr);
    post_kernel<<<TT, NTHR, postSmem>>>(Wout, bout, out);
}